// round 5
// baseline (speedup 1.0000x reference)
#include <cuda_runtime.h>
#include <cuda_bf16.h>
#include <cstdint>

#define N_TOK 65536
#define D_IN  1024
#define E_DIM 256
#define K_CB  1024
#define EPS   1e-5f
#define SLABS 64

// smem tile geometry: rows of 32 bf16 (64B) padded to 80B (LDSM conflict-free)
#define RB     80
#define MATB   (128 * RB)          // 10240
#define BUFB   (4 * MATB)          // 40960: Ah|Al|Bh|Bl
#define MM_SMEM (2 * BUFB + 2048)  // + hh_sm

// ================= scratch =================
__device__ float g_ps1[SLABS * D_IN];
__device__ float g_ps2[SLABS * D_IN];
__device__ float g_a[D_IN];
__device__ float g_bv[D_IN];
__device__ float g_b1p[E_DIM];
__device__ __nv_bfloat16 g_x_hi[(size_t)N_TOK * D_IN];    // 128 MB
__device__ __nv_bfloat16 g_x_lo[(size_t)N_TOK * D_IN];    // 128 MB
__device__ __nv_bfloat16 g_w1_hi[E_DIM * D_IN];
__device__ __nv_bfloat16 g_w1_lo[E_DIM * D_IN];
__device__ __nv_bfloat16 g_emb_hi[K_CB * E_DIM];
__device__ __nv_bfloat16 g_emb_lo[K_CB * E_DIM];
__device__ __nv_bfloat16 g_h_hi[(size_t)N_TOK * E_DIM];   // 32 MB
__device__ __nv_bfloat16 g_h_lo[(size_t)N_TOK * E_DIM];   // 32 MB
__device__ float g_hhp[2 * N_TOK];
__device__ float g_ee[K_CB];
__device__ unsigned long long g_amin[N_TOK];
__device__ int   g_hist[K_CB];
__device__ float g_scale2[E_DIM];
__device__ float g_shift2[E_DIM];
__device__ float g_qn[K_CB * E_DIM];
__device__ float g_ocb[(size_t)K_CB * D_IN];
__device__ double g_loss;

// ================= helpers =================
__device__ __forceinline__ uint32_t smem_u32(const void* p) {
    uint32_t a;
    asm("{ .reg .u64 t; cvta.to.shared.u64 t, %1; cvt.u32.u64 %0, t; }" : "=r"(a) : "l"(p));
    return a;
}
__device__ __forceinline__ uint32_t pack2(__nv_bfloat16 a, __nv_bfloat16 b) {
    __nv_bfloat162 t(a, b); return *(uint32_t*)&t;
}
__device__ __forceinline__ void bf16split(float v, __nv_bfloat16& hi, __nv_bfloat16& lo) {
    hi = __float2bfloat16_rn(v);
    lo = __float2bfloat16_rn(v - __bfloat162float(hi));
}
__device__ __forceinline__ void mma_bf16(float c[4], const uint32_t a[4], const uint32_t b[2]) {
    asm volatile(
        "mma.sync.aligned.m16n8k16.row.col.f32.bf16.bf16.f32 "
        "{%0,%1,%2,%3}, {%4,%5,%6,%7}, {%8,%9}, {%0,%1,%2,%3};"
        : "+f"(c[0]), "+f"(c[1]), "+f"(c[2]), "+f"(c[3])
        : "r"(a[0]), "r"(a[1]), "r"(a[2]), "r"(a[3]), "r"(b[0]), "r"(b[1]));
}
__device__ __forceinline__ unsigned long long packdi(float d, unsigned col) {
    unsigned u = __float_as_uint(d);
    u = (u & 0x80000000u) ? ~u : (u | 0x80000000u);
    return ((unsigned long long)u << 32) | col;
}
__device__ __forceinline__ void cp16(uint32_t s, const void* g) {
    asm volatile("cp.async.cg.shared.global [%0], [%1], 16;" :: "r"(s), "l"(g));
}
#define CP_COMMIT() asm volatile("cp.async.commit_group;" ::: "memory")
#define CP_WAIT0()  asm volatile("cp.async.wait_group 0;" ::: "memory")
#define LDSM4(d, a) \
    asm volatile("ldmatrix.sync.aligned.m8n8.x4.shared.b16 {%0,%1,%2,%3}, [%4];" \
        : "=r"((d)[0]), "=r"((d)[1]), "=r"((d)[2]), "=r"((d)[3]) : "r"(a))

// fill one buffer: 4 tiles of 128 rows x 32 bf16 (64B), 2x 16B copies per thread per tile
__device__ __forceinline__ void fill_tiles(uint32_t sbuf,
    const __nv_bfloat16* Ah, const __nv_bfloat16* Al, int ldA,
    const __nv_bfloat16* Bh, const __nv_bfloat16* Bl, int ldB, int kOff) {
    int tid = threadIdx.x;
#pragma unroll
    for (int j = 0; j < 2; j++) {
        int idx = tid * 2 + j;
        int row = idx >> 2, seg = idx & 3;
        uint32_t so = row * RB + seg * 16;
        const char* pa  = (const char*)(Ah + (size_t)row * ldA + kOff) + seg * 16;
        const char* pal = (const char*)(Al + (size_t)row * ldA + kOff) + seg * 16;
        const char* pb  = (const char*)(Bh + (size_t)row * ldB + kOff) + seg * 16;
        const char* pbl = (const char*)(Bl + (size_t)row * ldB + kOff) + seg * 16;
        cp16(sbuf + so,            pa);
        cp16(sbuf + MATB + so,     pal);
        cp16(sbuf + 2 * MATB + so, pb);
        cp16(sbuf + 3 * MATB + so, pbl);
    }
}

// bf16x3 HMMA mainloop: CTA 128x128, warp 64x32, K-chunk 32, cp.async 2-stage + ldmatrix
template<int CHUNKS>
__device__ __forceinline__ void hmma_loop(uint32_t sb,
    const __nv_bfloat16* Ah, const __nv_bfloat16* Al, int ldA,
    const __nv_bfloat16* Bh, const __nv_bfloat16* Bl, int ldB,
    float acc[4][4][4]) {
    int tid = threadIdx.x, lane = tid & 31, warp = tid >> 5;
    int wm = warp & 1, wn = warp >> 1;
    uint32_t aOff = (uint32_t)((wm * 64 + ((lane >> 3) & 1) * 8 + (lane & 7)) * RB + (lane >> 4) * 16);
    uint32_t bOff = (uint32_t)((wn * 32 + ((lane >> 4) & 1) * 8 + (lane & 7)) * RB + ((lane >> 3) & 1) * 16);

    fill_tiles(sb, Ah, Al, ldA, Bh, Bl, ldB, 0);
    CP_COMMIT();

    for (int c = 0; c < CHUNKS; c++) {
        uint32_t cb = sb + (uint32_t)(c & 1) * BUFB;
        CP_WAIT0();
        __syncthreads();
        if (c + 1 < CHUNKS) {
            fill_tiles(sb + (uint32_t)((c + 1) & 1) * BUFB, Ah, Al, ldA, Bh, Bl, ldB, (c + 1) * 32);
            CP_COMMIT();
        }
#pragma unroll
        for (int s = 0; s < 2; s++) {
            uint32_t sByte = s * 32;
            uint32_t ah[4][4], al[4][4];
#pragma unroll
            for (int mi = 0; mi < 4; mi++) {
                uint32_t ad = cb + aOff + mi * (16 * RB) + sByte;
                LDSM4(ah[mi], ad);
                LDSM4(al[mi], ad + MATB);
            }
#pragma unroll
            for (int p = 0; p < 2; p++) {
                uint32_t bd = cb + 2 * MATB + bOff + p * (16 * RB) + sByte;
                uint32_t bh[4], bl[4];
                LDSM4(bh, bd);
                LDSM4(bl, bd + MATB);
#pragma unroll
                for (int mi = 0; mi < 4; mi++)
#pragma unroll
                    for (int q = 0; q < 2; q++) {
                        mma_bf16(acc[mi][2 * p + q], ah[mi], &bh[q * 2]);
                        mma_bf16(acc[mi][2 * p + q], ah[mi], &bl[q * 2]);
                        mma_bf16(acc[mi][2 * p + q], al[mi], &bh[q * 2]);
                    }
            }
        }
        __syncthreads();
    }
}

// ================= producer kernels (split fused in) =================
__global__ void k_init() {
    int i = blockIdx.x * blockDim.x + threadIdx.x;
    g_amin[i] = 0xFFFFFFFFFFFFFFFFull;
    if (i < K_CB) g_hist[i] = 0;
    if (i == 0)   g_loss = 0.0;
}

__global__ void k_colstats(const float* __restrict__ x) {
    int col  = blockIdx.x * 256 + threadIdx.x;
    int slab = blockIdx.y;
    const float* p = x + (size_t)slab * 1024 * D_IN + col;
    __nv_bfloat16* xh = g_x_hi + (size_t)slab * 1024 * D_IN + col;
    __nv_bfloat16* xl = g_x_lo + (size_t)slab * 1024 * D_IN + col;
    float s = 0.f, s2 = 0.f;
#pragma unroll 4
    for (int r = 0; r < 1024; r++) {
        float v = p[(size_t)r * D_IN];
        s += v; s2 += v * v;
        __nv_bfloat16 hi, lo; bf16split(v, hi, lo);
        xh[(size_t)r * D_IN] = hi;
        xl[(size_t)r * D_IN] = lo;
    }
    g_ps1[slab * D_IN + col] = s;
    g_ps2[slab * D_IN + col] = s2;
}

__global__ void k_bn1fin(const float* __restrict__ gamma1, const float* __restrict__ beta1) {
    int col = blockIdx.x * 256 + threadIdx.x;
    float s = 0.f, s2 = 0.f;
    for (int i = 0; i < SLABS; i++) { s += g_ps1[i * D_IN + col]; s2 += g_ps2[i * D_IN + col]; }
    float mu  = s / (float)N_TOK;
    float var = s2 / (float)N_TOK - mu * mu;
    float a = gamma1[col] * rsqrtf(var + EPS);
    g_a[col]  = a;
    g_bv[col] = beta1[col] - mu * a;
}

__global__ void k_fold(const float* __restrict__ w1, const float* __restrict__ b1) {
    int e = blockIdx.x, t = threadIdx.x;
    float acc = 0.f;
#pragma unroll
    for (int j = 0; j < D_IN / 256; j++) {
        int d = j * 256 + t;
        float w = w1[(size_t)e * D_IN + d];
        float ws = w * g_a[d];
        __nv_bfloat16 hi, lo; bf16split(ws, hi, lo);
        g_w1_hi[(size_t)e * D_IN + d] = hi;
        g_w1_lo[(size_t)e * D_IN + d] = lo;
        acc += g_bv[d] * w;
    }
    __shared__ float sm[256];
    sm[t] = acc; __syncthreads();
    for (int s = 128; s > 0; s >>= 1) { if (t < s) sm[t] += sm[t + s]; __syncthreads(); }
    if (t == 0) g_b1p[e] = b1[e] + sm[0];
}

__global__ void k_ee(const float* __restrict__ emb) {
    int warp = threadIdx.x >> 5, lane = threadIdx.x & 31;
    int row = blockIdx.x * 8 + warp;
    const float* p = emb + (size_t)row * E_DIM;
    float s = 0.f;
#pragma unroll
    for (int c = lane; c < E_DIM; c += 32) {
        float v = p[c]; s += v * v;
        __nv_bfloat16 hi, lo; bf16split(v, hi, lo);
        g_emb_hi[(size_t)row * E_DIM + c] = hi;
        g_emb_lo[(size_t)row * E_DIM + c] = lo;
    }
#pragma unroll
    for (int o = 16; o > 0; o >>= 1) s += __shfl_down_sync(0xffffffffu, s, o);
    if (lane == 0) g_ee[row] = s;
}

// ================= GEMM1: h = x @ w1s^T + b1p (fused hh + split) =================
__global__ __launch_bounds__(256, 2) void k_mm1() {
    extern __shared__ char smc[];
    uint32_t sb = smem_u32(smc);
    float* hh_sm = (float*)(smc + 2 * BUFB);
    int tid = threadIdx.x, lane = tid & 31, warp = tid >> 5;
    int wm = warp & 1, wn = warp >> 1, g = lane >> 2, tig = lane & 3;

    float acc[4][4][4] = {};
    hmma_loop<32>(sb,
        g_x_hi + (size_t)blockIdx.x * 128 * D_IN,
        g_x_lo + (size_t)blockIdx.x * 128 * D_IN, D_IN,
        g_w1_hi + (size_t)blockIdx.y * 128 * D_IN,
        g_w1_lo + (size_t)blockIdx.y * 128 * D_IN, D_IN, acc);

    int by = blockIdx.y;
    float bv0[4], bv1[4];
#pragma unroll
    for (int ni = 0; ni < 4; ni++) {
        int colg = by * 128 + wn * 32 + ni * 8 + tig * 2;
        bv0[ni] = g_b1p[colg]; bv1[ni] = g_b1p[colg + 1];
    }
#pragma unroll
    for (int mi = 0; mi < 4; mi++) {
        int rloc = wm * 64 + mi * 16 + g;
        int rowg = blockIdx.x * 128 + rloc;
        float s0 = 0.f, s1 = 0.f;
#pragma unroll
        for (int ni = 0; ni < 4; ni++) {
            int colg = by * 128 + wn * 32 + ni * 8 + tig * 2;
            float v0 = acc[mi][ni][0] + bv0[ni];
            float v1 = acc[mi][ni][1] + bv1[ni];
            float v2 = acc[mi][ni][2] + bv0[ni];
            float v3 = acc[mi][ni][3] + bv1[ni];
            s0 += v0 * v0 + v1 * v1;
            s1 += v2 * v2 + v3 * v3;
            __nv_bfloat16 h0, h1, l0, l1;
            bf16split(v0, h0, l0); bf16split(v1, h1, l1);
            *(uint32_t*)(g_h_hi + (size_t)rowg * 256 + colg) = pack2(h0, h1);
            *(uint32_t*)(g_h_lo + (size_t)rowg * 256 + colg) = pack2(l0, l1);
            bf16split(v2, h0, l0); bf16split(v3, h1, l1);
            *(uint32_t*)(g_h_hi + (size_t)(rowg + 8) * 256 + colg) = pack2(h0, h1);
            *(uint32_t*)(g_h_lo + (size_t)(rowg + 8) * 256 + colg) = pack2(l0, l1);
        }
        s0 += __shfl_xor_sync(0xffffffffu, s0, 1);
        s0 += __shfl_xor_sync(0xffffffffu, s0, 2);
        s1 += __shfl_xor_sync(0xffffffffu, s1, 1);
        s1 += __shfl_xor_sync(0xffffffffu, s1, 2);
        if (tig == 0) { hh_sm[wn * 128 + rloc] = s0; hh_sm[wn * 128 + rloc + 8] = s1; }
    }
    __syncthreads();
    if (tid < 128) {
        float hh = hh_sm[tid] + hh_sm[128 + tid] + hh_sm[256 + tid] + hh_sm[384 + tid];
        g_hhp[(size_t)by * N_TOK + blockIdx.x * 128 + tid] = hh;
    }
}

// ================= dist GEMM + fused argmin =================
__global__ __launch_bounds__(256, 2) void k_dist() {
    extern __shared__ char smc[];
    uint32_t sb = smem_u32(smc);
    int tid = threadIdx.x, lane = tid & 31, warp = tid >> 5;
    int wm = warp & 1, wn = warp >> 1, g = lane >> 2, tig = lane & 3;

    float acc[4][4][4] = {};
    hmma_loop<8>(sb,
        g_h_hi + (size_t)blockIdx.x * 128 * E_DIM,
        g_h_lo + (size_t)blockIdx.x * 128 * E_DIM, E_DIM,
        g_emb_hi + (size_t)blockIdx.y * 128 * E_DIM,
        g_emb_lo + (size_t)blockIdx.y * 128 * E_DIM, E_DIM, acc);

    int by = blockIdx.y;
#pragma unroll
    for (int mi = 0; mi < 4; mi++) {
        int rowg = blockIdx.x * 128 + wm * 64 + mi * 16 + g;
        float hh0 = g_hhp[rowg] + g_hhp[N_TOK + rowg];
        float hh1 = g_hhp[rowg + 8] + g_hhp[N_TOK + rowg + 8];
        unsigned long long b0 = ~0ull, b1 = ~0ull;
#pragma unroll
        for (int ni = 0; ni < 4; ni++) {
            int colg = by * 128 + wn * 32 + ni * 8 + tig * 2;
            float e0 = g_ee[colg], e1 = g_ee[colg + 1];
            float d0 = __fsub_rn(__fadd_rn(hh0, e0), __fmul_rn(2.0f, acc[mi][ni][0]));
            float d1 = __fsub_rn(__fadd_rn(hh0, e1), __fmul_rn(2.0f, acc[mi][ni][1]));
            float d2 = __fsub_rn(__fadd_rn(hh1, e0), __fmul_rn(2.0f, acc[mi][ni][2]));
            float d3 = __fsub_rn(__fadd_rn(hh1, e1), __fmul_rn(2.0f, acc[mi][ni][3]));
            unsigned long long p;
            p = packdi(d0, colg);     if (p < b0) b0 = p;
            p = packdi(d1, colg + 1); if (p < b0) b0 = p;
            p = packdi(d2, colg);     if (p < b1) b1 = p;
            p = packdi(d3, colg + 1); if (p < b1) b1 = p;
        }
        unsigned long long t;
        t = __shfl_xor_sync(0xffffffffu, b0, 1); if (t < b0) b0 = t;
        t = __shfl_xor_sync(0xffffffffu, b0, 2); if (t < b0) b0 = t;
        t = __shfl_xor_sync(0xffffffffu, b1, 1); if (t < b1) b1 = t;
        t = __shfl_xor_sync(0xffffffffu, b1, 2); if (t < b1) b1 = t;
        if (tig == 0) {
            atomicMin(&g_amin[rowg], b0);
            atomicMin(&g_amin[rowg + 8], b1);
        }
    }
}

// ================= remaining pipeline (validated) =================
__global__ void k_histo() {
    __shared__ int sh[K_CB];
    int t = threadIdx.x;
    for (int i = t; i < K_CB; i += 256) sh[i] = 0;
    __syncthreads();
    int n = blockIdx.x * 256 + t;
    int idx = (int)(g_amin[n] & 0xFFFFFFFFull);
    atomicAdd(&sh[idx], 1);
    __syncthreads();
    for (int i = t; i < K_CB; i += 256) if (sh[i]) atomicAdd(&g_hist[i], sh[i]);
}

__global__ void k_bn2(const float* __restrict__ emb,
                      const float* __restrict__ gamma2, const float* __restrict__ beta2) {
    int e = blockIdx.x, t = threadIdx.x;
    float s1 = 0.f, s2 = 0.f;
#pragma unroll
    for (int j = 0; j < 4; j++) {
        int k = j * 256 + t;
        float c = (float)g_hist[k];
        float v = emb[(size_t)k * E_DIM + e];
        s1 += c * v; s2 += c * v * v;
    }
    __shared__ float a1[256], a2[256];
    a1[t] = s1; a2[t] = s2; __syncthreads();
    for (int s = 128; s > 0; s >>= 1) {
        if (t < s) { a1[t] += a1[t + s]; a2[t] += a2[t + s]; }
        __syncthreads();
    }
    if (t == 0) {
        float mu  = a1[0] / (float)N_TOK;
        float var = a2[0] / (float)N_TOK - mu * mu;
        float sc = gamma2[e] * rsqrtf(var + EPS);
        g_scale2[e] = sc;
        g_shift2[e] = beta2[e] - mu * sc;
    }
}

__global__ void k_qn(const float* __restrict__ emb) {
    int i = blockIdx.x * 256 + threadIdx.x;
    int e = i & (E_DIM - 1);
    g_qn[i] = emb[i] * g_scale2[e] + g_shift2[e];
}

__global__ void k_gemm2(const float* __restrict__ w2, const float* __restrict__ b2) {
    __shared__ float As[16][128];
    __shared__ float Bs[16][128];
    float acc[8][8] = {};
    int tid = threadIdx.x;
    int tx = tid & 15, ty = tid >> 4;
    const float* Ab = g_qn + (size_t)(blockIdx.x * 128) * E_DIM;
    const float* Bb = w2 + (size_t)(blockIdx.y * 128) * E_DIM;
    for (int k0 = 0; k0 < E_DIM; k0 += 16) {
#pragma unroll
        for (int i = 0; i < 2; i++) {
            int id  = tid + i * 256;
            int row = id >> 2;
            int kq  = (id & 3) << 2;
            float4 va = *(const float4*)(Ab + (size_t)row * E_DIM + k0 + kq);
            As[kq + 0][row] = va.x; As[kq + 1][row] = va.y;
            As[kq + 2][row] = va.z; As[kq + 3][row] = va.w;
            float4 vb = *(const float4*)(Bb + (size_t)row * E_DIM + k0 + kq);
            Bs[kq + 0][row] = vb.x; Bs[kq + 1][row] = vb.y;
            Bs[kq + 2][row] = vb.z; Bs[kq + 3][row] = vb.w;
        }
        __syncthreads();
#pragma unroll
        for (int kk = 0; kk < 16; kk++) {
            float ra[8], rb[8];
            *(float4*)&ra[0] = *(const float4*)&As[kk][ty * 8];
            *(float4*)&ra[4] = *(const float4*)&As[kk][ty * 8 + 4];
            *(float4*)&rb[0] = *(const float4*)&Bs[kk][tx * 8];
            *(float4*)&rb[4] = *(const float4*)&Bs[kk][tx * 8 + 4];
#pragma unroll
            for (int i = 0; i < 8; i++)
#pragma unroll
                for (int j = 0; j < 8; j++)
                    acc[i][j] += ra[i] * rb[j];
        }
        __syncthreads();
    }
    int colBase = blockIdx.y * 128 + tx * 8;
#pragma unroll
    for (int i = 0; i < 8; i++) {
        size_t row = (size_t)blockIdx.x * 128 + ty * 8 + i;
        float4 v0, v1;
        v0.x = acc[i][0] + b2[colBase + 0]; v0.y = acc[i][1] + b2[colBase + 1];
        v0.z = acc[i][2] + b2[colBase + 2]; v0.w = acc[i][3] + b2[colBase + 3];
        v1.x = acc[i][4] + b2[colBase + 4]; v1.y = acc[i][5] + b2[colBase + 5];
        v1.z = acc[i][6] + b2[colBase + 6]; v1.w = acc[i][7] + b2[colBase + 7];
        *(float4*)(g_ocb + row * D_IN + colBase)     = v0;
        *(float4*)(g_ocb + row * D_IN + colBase + 4) = v1;
    }
}

__global__ void k_final(const float* __restrict__ x, float* __restrict__ out) {
    int t = threadIdx.x;
    float* outq = out + 1;
    double accd = 0.0;
#pragma unroll
    for (int r = 0; r < 8; r++) {
        int n = blockIdx.x * 8 + r;
        int idx = (int)(g_amin[n] & 0xFFFFFFFFull);
        float4 q  = ((const float4*)(g_ocb + (size_t)idx * D_IN))[t];
        float4 xv = ((const float4*)(x + (size_t)n * D_IN))[t];
        float dx = __fsub_rn(q.x, xv.x);
        float dy = __fsub_rn(q.y, xv.y);
        float dz = __fsub_rn(q.z, xv.z);
        float dw = __fsub_rn(q.w, xv.w);
        float* o = outq + (size_t)n * D_IN + t * 4;
        o[0] = __fadd_rn(xv.x, dx);
        o[1] = __fadd_rn(xv.y, dy);
        o[2] = __fadd_rn(xv.z, dz);
        o[3] = __fadd_rn(xv.w, dw);
        accd += (double)dx * dx + (double)dy * dy + (double)dz * dz + (double)dw * dw;
    }
    __shared__ double sd[256];
    sd[t] = accd; __syncthreads();
    for (int s = 128; s > 0; s >>= 1) { if (t < s) sd[t] += sd[t + s]; __syncthreads(); }
    if (t == 0) atomicAdd(&g_loss, sd[0]);
}

__global__ void k_small(float* __restrict__ out) {
    int i = blockIdx.x * 256 + threadIdx.x;
    size_t OFF_U = 1 + (size_t)N_TOK * D_IN;
    if (i == 0) out[0] = (float)(1.25 * g_loss / ((double)N_TOK * (double)D_IN));
    if (i < K_CB) out[OFF_U + i] = (float)g_hist[i] / (float)N_TOK;
}

__global__ void k_embcopy(const float* __restrict__ emb, float* __restrict__ out) {
    size_t OFF_E = 1 + (size_t)N_TOK * D_IN + K_CB;
    int i = blockIdx.x * 256 + threadIdx.x;
    out[OFF_E + i] = emb[i];
}

// ================= launch =================
extern "C" void kernel_launch(void* const* d_in, const int* in_sizes, int n_in,
                              void* d_out, int out_size) {
    (void)in_sizes; (void)n_in; (void)out_size;
    const float* x      = (const float*)d_in[0];
    const float* emb    = (const float*)d_in[1];
    const float* w1     = (const float*)d_in[2];
    const float* b1     = (const float*)d_in[3];
    const float* w2     = (const float*)d_in[4];
    const float* b2     = (const float*)d_in[5];
    const float* gamma1 = (const float*)d_in[6];
    const float* beta1  = (const float*)d_in[7];
    const float* gamma2 = (const float*)d_in[8];
    const float* beta2  = (const float*)d_in[9];
    float* out = (float*)d_out;

    cudaFuncSetAttribute(k_mm1,  cudaFuncAttributeMaxDynamicSharedMemorySize, MM_SMEM);
    cudaFuncSetAttribute(k_dist, cudaFuncAttributeMaxDynamicSharedMemorySize, MM_SMEM);

    k_init<<<256, 256>>>();
    k_colstats<<<dim3(D_IN / 256, SLABS), 256>>>(x);
    k_bn1fin<<<D_IN / 256, 256>>>(gamma1, beta1);
    k_fold<<<E_DIM, 256>>>(w1, b1);
    k_ee<<<K_CB / 8, 256>>>(emb);
    k_mm1<<<dim3(N_TOK / 128, 2), 256, MM_SMEM>>>();
    k_dist<<<dim3(N_TOK / 128, K_CB / 128), 256, MM_SMEM>>>();
    k_histo<<<N_TOK / 256, 256>>>();
    k_bn2<<<E_DIM, 256>>>(emb, gamma2, beta2);
    k_qn<<<(K_CB * E_DIM) / 256, 256>>>(emb);
    k_gemm2<<<dim3(K_CB / 128, D_IN / 128), 256>>>(w2, b2);
    k_final<<<N_TOK / 8, 256>>>(x, out);
    k_small<<<4, 256>>>(out);
    k_embcopy<<<(K_CB * E_DIM) / 256, 256>>>(emb, out);
}